// round 2
// baseline (speedup 1.0000x reference)
#include <cuda_runtime.h>
#include <cuda_fp16.h>
#include <cstdint>
#include <math.h>

// ============================================================================
// HebbianPlasticLayer on sm_103 (base target -> no tcgen05; classic mma.sync).
//   y_slow = x @ W^T + bias
//   s      = (x*x/(||x||+1e-8)) @ sigmoid(alpha)^T
//   out    = y_slow + eta * tanh(y_slow) * s
// B = DIN = DOUT = 4096.
//
// Two fp16 NT GEMMs (fp32 accum) via mma.sync.m16n8k16, Ampere-style
// 3-stage cp.async pipeline, SW128-swizzled smem, ldmatrix operand loads,
// fused epilogues (bias add / tanh-plastic combine).
// ============================================================================

static constexpr int ND = 4096;
static constexpr int BM = 128, BN = 128, BK = 64;   // 64 fp16 = 128 B rows
static constexpr int STAGES = 3;
static constexpr int KTILES = ND / BK;              // 64
static constexpr int STAGE_BYTES = (BM + BN) * BK * 2;  // 32768
static constexpr int OFF_B = BM * BK * 2;               // 16384
static constexpr int SMEM_BYTES = STAGES * STAGE_BYTES; // 98304

// ---------------- scratch (static device globals; no runtime alloc) ---------
__device__ __half g_xh [(size_t)ND * ND];   // fp16(x)
__device__ __half g_xxh[(size_t)ND * ND];   // fp16(x*x*inv_norm)
__device__ __half g_wh [(size_t)ND * ND];   // fp16(W)
__device__ __half g_ah [(size_t)ND * ND];   // fp16(sigmoid(alpha))
__device__ float  g_yslow[(size_t)ND * ND];
__device__ float  g_inv[ND];

// ---------------- small helpers ---------------------------------------------
__device__ __forceinline__ uint32_t smem_u32_of(const void* p) {
    uint32_t a;
    asm("{ .reg .u64 t; cvta.to.shared.u64 t, %1; cvt.u32.u64 %0, t; }"
        : "=r"(a) : "l"(p));
    return a;
}

__device__ __forceinline__ void cp16(uint32_t dst, const void* src) {
    asm volatile("cp.async.cg.shared.global [%0], [%1], 16;" :: "r"(dst), "l"(src));
}

__device__ __forceinline__ void ldsm_x4(uint32_t r[4], uint32_t addr) {
    asm volatile("ldmatrix.sync.aligned.m8n8.x4.shared.b16 {%0,%1,%2,%3}, [%4];"
                 : "=r"(r[0]), "=r"(r[1]), "=r"(r[2]), "=r"(r[3]) : "r"(addr));
}

__device__ __forceinline__ void mma16816(float c[4], const uint32_t a[4],
                                         uint32_t b0, uint32_t b1) {
    asm volatile(
        "mma.sync.aligned.m16n8k16.row.col.f32.f16.f16.f32 "
        "{%0,%1,%2,%3}, {%4,%5,%6,%7}, {%8,%9}, {%0,%1,%2,%3};"
        : "+f"(c[0]), "+f"(c[1]), "+f"(c[2]), "+f"(c[3])
        : "r"(a[0]), "r"(a[1]), "r"(a[2]), "r"(a[3]), "r"(b0), "r"(b1));
}

// accurate cheap tanh: 1 - 2/(e^{2y}+1), MUFU ex2 + rcp (err ~1e-6)
__device__ __forceinline__ float fast_tanh(float y) {
    float e = __expf(2.0f * y);
    return 1.0f - __fdividef(2.0f, e + 1.0f);
}

// ---------------- prep kernels -----------------------------------------------
__global__ void rownorm_kernel(const float* __restrict__ x) {
    const int row = blockIdx.x;
    const float4* xr = (const float4*)(x + (size_t)row * ND);
    float s = 0.f;
    for (int i = threadIdx.x; i < ND / 4; i += blockDim.x) {
        float4 v = xr[i];
        s += v.x * v.x + v.y * v.y + v.z * v.z + v.w * v.w;
    }
    for (int o = 16; o; o >>= 1) s += __shfl_down_sync(0xFFFFFFFFu, s, o);
    __shared__ float red[8];
    if ((threadIdx.x & 31) == 0) red[threadIdx.x >> 5] = s;
    __syncthreads();
    if (threadIdx.x < 8) {
        float t = red[threadIdx.x];
        for (int o = 4; o; o >>= 1) t += __shfl_down_sync(0xFFu, t, o);
        if (threadIdx.x == 0) g_inv[row] = 1.f / (sqrtf(t) + 1e-8f);
    }
}

__global__ void prep_x_kernel(const float* __restrict__ x) {
    const size_t i = (size_t)blockIdx.x * blockDim.x + threadIdx.x;  // float4 idx
    float4 v = ((const float4*)x)[i];
    const float inv = g_inv[i >> 10];            // 1024 float4 per row
    __half2 h0 = __floats2half2_rn(v.x, v.y);
    __half2 h1 = __floats2half2_rn(v.z, v.w);
    __half2 q0 = __floats2half2_rn(v.x * v.x * inv, v.y * v.y * inv);
    __half2 q1 = __floats2half2_rn(v.z * v.z * inv, v.w * v.w * inv);
    ((__half2*)g_xh)[2 * i + 0]  = h0;
    ((__half2*)g_xh)[2 * i + 1]  = h1;
    ((__half2*)g_xxh)[2 * i + 0] = q0;
    ((__half2*)g_xxh)[2 * i + 1] = q1;
}

__global__ void prep_w_kernel(const float* __restrict__ W) {
    const size_t i = (size_t)blockIdx.x * blockDim.x + threadIdx.x;
    float4 v = ((const float4*)W)[i];
    ((__half2*)g_wh)[2 * i + 0] = __floats2half2_rn(v.x, v.y);
    ((__half2*)g_wh)[2 * i + 1] = __floats2half2_rn(v.z, v.w);
}

__global__ void prep_a_kernel(const float* __restrict__ alpha) {
    const size_t i = (size_t)blockIdx.x * blockDim.x + threadIdx.x;
    float4 v = ((const float4*)alpha)[i];
    float s0 = __fdividef(1.f, 1.f + __expf(-v.x));
    float s1 = __fdividef(1.f, 1.f + __expf(-v.y));
    float s2 = __fdividef(1.f, 1.f + __expf(-v.z));
    float s3 = __fdividef(1.f, 1.f + __expf(-v.w));
    ((__half2*)g_ah)[2 * i + 0] = __floats2half2_rn(s0, s1);
    ((__half2*)g_ah)[2 * i + 1] = __floats2half2_rn(s2, s3);
}

// ---------------- GEMM -------------------------------------------------------
// load one BK stage of A (BM x BK) and B (BN x BK), SW128 swizzled
__device__ __forceinline__ void load_stage(uint32_t smem_u32, int buf,
                                           const char* gA, const char* gB,
                                           int ks, int tid)
{
    const uint32_t sb = smem_u32 + buf * STAGE_BYTES;
    const size_t kof = (size_t)ks * (BK * 2);        // bytes into K
#pragma unroll
    for (int i = 0; i < 4; i++) {                    // A: 1024 chunks of 16B
        int c = tid + (i << 8);
        int r = c >> 3, kc = (c & 7) << 4;
        uint32_t off = (uint32_t)(r << 7) + kc;
        uint32_t sw = off ^ ((off >> 3) & 0x70);
        cp16(sb + sw, gA + (size_t)r * (ND * 2) + kof + kc);
    }
#pragma unroll
    for (int i = 0; i < 4; i++) {                    // B: 1024 chunks of 16B
        int c = tid + (i << 8);
        int r = c >> 3, kc = (c & 7) << 4;
        uint32_t off = (uint32_t)(r << 7) + kc;
        uint32_t sw = off ^ ((off >> 3) & 0x70);
        cp16(sb + OFF_B + sw, gB + (size_t)r * (ND * 2) + kof + kc);
    }
}

__global__ void __launch_bounds__(256)
gemm_kernel(const __half* __restrict__ A, const __half* __restrict__ Bm,
            const float* __restrict__ bias, const float* __restrict__ eta_ptr,
            float* __restrict__ dst, int mode)
{
    extern __shared__ char smem[];
    const uint32_t smem_u32 = smem_u32_of(smem);
    const int tid = threadIdx.x;
    const int lane = tid & 31;
    const int wid = tid >> 5;
    const int warp_m = wid & 1;           // 2 x 64 rows
    const int warp_n = wid >> 1;          // 4 x 32 cols

    const char* gA = (const char*)A + (size_t)blockIdx.y * BM * (ND * 2);
    const char* gB = (const char*)Bm + (size_t)blockIdx.x * BN * (ND * 2);

    // per-thread ldmatrix address components
    uint32_t a_row[4], a_xor[4];
#pragma unroll
    for (int mt = 0; mt < 4; mt++) {
        int r = warp_m * 64 + mt * 16 + (lane & 15);
        a_row[mt] = (uint32_t)(r << 7);
        a_xor[mt] = (uint32_t)((r & 7) << 4);
    }
    const uint32_t a_half = (uint32_t)((lane >> 4) << 4);
    uint32_t b_row[2], b_xor[2];
#pragma unroll
    for (int p = 0; p < 2; p++) {
        int r = warp_n * 32 + p * 16 + ((lane >> 4) << 3) + (lane & 7);
        b_row[p] = (uint32_t)(r << 7);
        b_xor[p] = (uint32_t)((r & 7) << 4);
    }
    const uint32_t b_half = (uint32_t)(((lane >> 3) & 1) << 4);

    float c[4][4][4];
#pragma unroll
    for (int i = 0; i < 4; i++)
#pragma unroll
        for (int j = 0; j < 4; j++)
#pragma unroll
            for (int k = 0; k < 4; k++) c[i][j][k] = 0.f;

    load_stage(smem_u32, 0, gA, gB, 0, tid);
    asm volatile("cp.async.commit_group;" ::: "memory");
    load_stage(smem_u32, 1, gA, gB, 1, tid);
    asm volatile("cp.async.commit_group;" ::: "memory");

    int buf = 0;
#pragma unroll 1
    for (int ks = 0; ks < KTILES; ks++) {
        if (ks < KTILES - 2) asm volatile("cp.async.wait_group 1;" ::: "memory");
        else                 asm volatile("cp.async.wait_group 0;" ::: "memory");
        __syncthreads();

        if (ks + 2 < KTILES) {
            int nbuf = buf + 2; if (nbuf >= STAGES) nbuf -= STAGES;
            load_stage(smem_u32, nbuf, gA, gB, ks + 2, tid);
            asm volatile("cp.async.commit_group;" ::: "memory");
        }

        const uint32_t sbA = smem_u32 + buf * STAGE_BYTES;
        const uint32_t sbB = sbA + OFF_B;
#pragma unroll
        for (int kk = 0; kk < 4; kk++) {
            const uint32_t kb = (uint32_t)(kk << 5);
            uint32_t a[4][4];
#pragma unroll
            for (int mt = 0; mt < 4; mt++)
                ldsm_x4(a[mt], sbA + a_row[mt] + (((kb + a_half)) ^ a_xor[mt]));
            uint32_t b[4][2];
#pragma unroll
            for (int p = 0; p < 2; p++) {
                uint32_t r[4];
                ldsm_x4(r, sbB + b_row[p] + (((kb + b_half)) ^ b_xor[p]));
                b[2 * p][0] = r[0]; b[2 * p][1] = r[1];
                b[2 * p + 1][0] = r[2]; b[2 * p + 1][1] = r[3];
            }
#pragma unroll
            for (int mt = 0; mt < 4; mt++)
#pragma unroll
                for (int nt = 0; nt < 4; nt++)
                    mma16816(c[mt][nt], a[mt], b[nt][0], b[nt][1]);
        }
        buf++; if (buf >= STAGES) buf = 0;
    }

    // ---------------- epilogue ----------------
    const int row0 = blockIdx.y * BM + warp_m * 64 + (lane >> 2);
    const int col0 = blockIdx.x * BN + warp_n * 32 + ((lane & 3) << 1);
    const float eta = (mode == 1) ? *eta_ptr : 0.f;

#pragma unroll
    for (int mt = 0; mt < 4; mt++) {
#pragma unroll
        for (int nt = 0; nt < 4; nt++) {
            const int col = col0 + nt * 8;
            const int r0 = row0 + mt * 16;
            const int r1 = r0 + 8;
            if (mode == 0) {
                float b0 = __ldg(&bias[col]);
                float b1 = __ldg(&bias[col + 1]);
                float2 v0 = make_float2(c[mt][nt][0] + b0, c[mt][nt][1] + b1);
                float2 v1 = make_float2(c[mt][nt][2] + b0, c[mt][nt][3] + b1);
                *(float2*)&dst[(size_t)r0 * ND + col] = v0;
                *(float2*)&dst[(size_t)r1 * ND + col] = v1;
            } else {
                float2 y0 = *(const float2*)&g_yslow[(size_t)r0 * ND + col];
                float2 y1 = *(const float2*)&g_yslow[(size_t)r1 * ND + col];
                float2 v0, v1;
                v0.x = y0.x + eta * fast_tanh(y0.x) * c[mt][nt][0];
                v0.y = y0.y + eta * fast_tanh(y0.y) * c[mt][nt][1];
                v1.x = y1.x + eta * fast_tanh(y1.x) * c[mt][nt][2];
                v1.y = y1.y + eta * fast_tanh(y1.y) * c[mt][nt][3];
                *(float2*)&dst[(size_t)r0 * ND + col] = v0;
                *(float2*)&dst[(size_t)r1 * ND + col] = v1;
            }
        }
    }
}

// ---------------- launch -----------------------------------------------------
extern "C" void kernel_launch(void* const* d_in, const int* in_sizes, int n_in,
                              void* d_out, int out_size)
{
    // metadata order: x, W, alpha, eta, bias — resolve defensively by size
    const float* big[3] = {nullptr, nullptr, nullptr};
    const float* eta = nullptr;
    const float* bias = nullptr;
    int nb = 0;
    for (int i = 0; i < n_in; i++) {
        if (in_sizes[i] == 1) eta = (const float*)d_in[i];
        else if (in_sizes[i] == ND) bias = (const float*)d_in[i];
        else if (nb < 3) big[nb++] = (const float*)d_in[i];
    }
    const float* x = big[0];
    const float* W = big[1];
    const float* alpha = big[2];
    float* out = (float*)d_out;

    cudaFuncSetAttribute(gemm_kernel, cudaFuncAttributeMaxDynamicSharedMemorySize,
                         SMEM_BYTES);

    rownorm_kernel<<<ND, 256>>>(x);
    const int n4blocks = (ND * (ND / 4)) / 256;          // 16384
    prep_x_kernel<<<n4blocks, 256>>>(x);
    prep_w_kernel<<<n4blocks, 256>>>(W);
    prep_a_kernel<<<n4blocks, 256>>>(alpha);

    __half *xh, *xxh, *wh, *ah;
    float *yslow;
    cudaGetSymbolAddress((void**)&xh, g_xh);
    cudaGetSymbolAddress((void**)&xxh, g_xxh);
    cudaGetSymbolAddress((void**)&wh, g_wh);
    cudaGetSymbolAddress((void**)&ah, g_ah);
    cudaGetSymbolAddress((void**)&yslow, g_yslow);

    dim3 grid(ND / BN, ND / BM);                         // (32, 32)
    gemm_kernel<<<grid, 256, SMEM_BYTES>>>(xh, wh, bias, eta, yslow, 0);
    gemm_kernel<<<grid, 256, SMEM_BYTES>>>(xxh, ah, bias, eta, out, 1);
}